// round 5
// baseline (speedup 1.0000x reference)
#include <cuda_runtime.h>

typedef unsigned long long ull;

// ---------------- scratch ----------------
__device__ float g_Gpart[8 * 64 * 64 * 64];   // split-K gram partials, row-major per chunk
__device__ float g_m1part[8 * 64 * 64];       // token-sum partials
__device__ float g_Mdup[8 * 64 * 128];        // mixing matrix [b][j][2s], duplicated {m,m}
__device__ float g_cst[1];

__device__ __forceinline__ void ffma2(ull& d, ull a, ull b) {
    asm("fma.rn.f32x2 %0, %1, %2, %0;" : "+l"(d) : "l"(a), "l"(b));
}
__device__ __forceinline__ ull pack2(float x, float y) {
    ull r; asm("mov.b64 %0, {%1, %2};" : "=l"(r) : "f"(x), "f"(y)); return r;
}
__device__ __forceinline__ ull add2(ull a, ull b) {
    ull r; asm("add.rn.f32x2 %0, %1, %2;" : "=l"(r) : "l"(a), "l"(b)); return r;
}

// ---------------- K1: Gram partials ----------------
// grid 512 (b*64+y), 128 threads. T[p][token] stride 68 (mid-pad 4 after col 31).
// Thread (ti,tj): rows 8ti..8ti+7 (dup'd via mov), cols 4tj..4tj+3 (natural pairs).
__global__ __launch_bounds__(128) void gram_kernel(const float* __restrict__ x) {
    int b = blockIdx.x >> 6, y = blockIdx.x & 63;
    __shared__ __align__(16) float T[64 * 68];
    const float* xb = x + b * 262144 + y * 512;
    int tid = threadIdx.x;

    // fill via 4x4 register transpose (coalesced LDG.128)
    #pragma unroll
    for (int t = 0; t < 2; ++t) {
        int tile = tid + 128 * t;
        int c = tile & 15, jg = tile >> 4;        // c: p-group, jg: token-group
        int j0 = 4 * jg;
        float4 q0 = *(const float4*)(xb + ((j0    ) >> 3) * 32768 + ((j0    ) & 7) * 64 + 4 * c);
        float4 q1 = *(const float4*)(xb + ((j0 + 1) >> 3) * 32768 + ((j0 + 1) & 7) * 64 + 4 * c);
        float4 q2 = *(const float4*)(xb + ((j0 + 2) >> 3) * 32768 + ((j0 + 2) & 7) * 64 + 4 * c);
        float4 q3 = *(const float4*)(xb + ((j0 + 3) >> 3) * 32768 + ((j0 + 3) & 7) * 64 + 4 * c);
        int colblk = 4 * jg + (jg >= 8 ? 4 : 0);
        float* d0 = &T[(4 * c) * 68 + colblk];
        *(float4*)(d0)       = make_float4(q0.x, q1.x, q2.x, q3.x);
        *(float4*)(d0 + 68)  = make_float4(q0.y, q1.y, q2.y, q3.y);
        *(float4*)(d0 + 136) = make_float4(q0.z, q1.z, q2.z, q3.z);
        *(float4*)(d0 + 204) = make_float4(q0.w, q1.w, q2.w, q3.w);
    }
    __syncthreads();

    int ti = tid >> 4, tj = tid & 15;
    int aoff = 8 * ti + (ti >= 4 ? 4 : 0);      // 8-float row block (contiguous incl. pad rule)
    int boff = 4 * tj + (tj >= 8 ? 4 : 0);
    ull acc[8][2];
    #pragma unroll
    for (int u = 0; u < 8; ++u) { acc[u][0] = 0ull; acc[u][1] = 0ull; }

    #pragma unroll 4
    for (int p = 0; p < 64; ++p) {
        const float* row = &T[p * 68];
        ulonglong2 bv = *(const ulonglong2*)(row + boff);   // cols: {b0,b1},{b2,b3}
        float4 a0 = *(const float4*)(row + aoff);           // rows (broadcast per phase)
        float4 a1 = *(const float4*)(row + aoff + 4);
        float av[8] = {a0.x, a0.y, a0.z, a0.w, a1.x, a1.y, a1.z, a1.w};
        #pragma unroll
        for (int u = 0; u < 8; ++u) {
            ull ad = pack2(av[u], av[u]);
            ffma2(acc[u][0], ad, bv.x);
            ffma2(acc[u][1], ad, bv.y);
        }
    }

    // m1 partial (conflict-free column sums)
    if (tid < 64) {
        float s = 0.f;
        int o = tid + (tid >= 32 ? 4 : 0);
        #pragma unroll 8
        for (int p = 0; p < 64; ++p) s += T[p * 68 + o];
        g_m1part[(b * 64 + y) * 64 + tid] = s;
    }

    float* gp = &g_Gpart[(b * 64 + y) * 4096];
    #pragma unroll
    for (int u = 0; u < 8; ++u)
        *(ulonglong2*)(gp + (8 * ti + u) * 64 + 4 * tj) = make_ulonglong2(acc[u][0], acc[u][1]);
}

// ---------------- K2: consts + reduce + softmax + duplicated/transposed M ----------------
// grid (8 batches, 16 row-groups of 4), 256 threads.
__global__ __launch_bounds__(256) void attn_kernel(
        const float* __restrict__ w1, const float* __restrict__ b1,
        const float* __restrict__ wqkv, const float* __restrict__ wproj,
        const float* __restrict__ bproj, const float* __restrict__ w2,
        const float* __restrict__ b2) {
    int b = blockIdx.x, i0 = blockIdx.y * 4, tid = threadIdx.x;
    __shared__ float A[96], B0[96], tC[32];
    __shared__ float sal[4], sbe[4], sga[4], sde[4], swh[4];
    __shared__ float Gs[256], m1s[64];

    // weight collapse (tiny, redundant per block)
    if (tid < 96) {
        float a = 0.f, bb = 0.f;
        #pragma unroll
        for (int c = 0; c < 32; ++c) {
            float wv = wqkv[tid * 32 + c];
            a += wv * w1[c];
            bb += wv * b1[c];
        }
        A[tid] = a; B0[tid] = bb;
    }
    if (tid >= 128 && tid < 160) {
        int c = tid - 128;
        float s = 0.f;
        #pragma unroll
        for (int o = 0; o < 32; ++o) s += w2[o] * wproj[o * 32 + c];
        tC[c] = s;
    }
    __syncthreads();
    if (tid < 4) {
        float al = 0.f, be = 0.f, ga = 0.f, de = 0.f, wh = 0.f;
        #pragma unroll
        for (int dd = 0; dd < 8; ++dd) {
            int c = tid * 8 + dd;
            float aq = A[c], ak = A[32 + c], bq = B0[c], bk = B0[32 + c];
            al += aq * ak; be += aq * bk; ga += bq * ak; de += bq * bk;
            wh += tC[c] * A[64 + c];
        }
        sal[tid] = al; sbe[tid] = be; sga[tid] = ga; sde[tid] = de; swh[tid] = wh;
    }
    if (tid == 4) {
        float c = b2[0];
        #pragma unroll
        for (int o = 0; o < 32; ++o) c += w2[o] * bproj[o];
        #pragma unroll
        for (int cc = 0; cc < 32; ++cc) c += tC[cc] * B0[64 + cc];
        g_cst[0] = c;
    }

    // reduce 4 Gram rows (64-deep split-K) + m1
    {
        const float* gp = &g_Gpart[b * 64 * 4096 + i0 * 64];
        float s = 0.f;
        #pragma unroll 8
        for (int c = 0; c < 64; ++c) s += gp[c * 4096 + tid];
        Gs[tid] = s;
    }
    if (tid < 64) {
        const float* mp = &g_m1part[b * 64 * 64];
        float s = 0.f;
        #pragma unroll 8
        for (int c = 0; c < 64; ++c) s += mp[c * 64 + tid];
        m1s[tid] = s;
    }
    __syncthreads();

    int w = tid >> 5, l = tid & 31;
    if (w < 4) {
        const float scale = 1.0f / (4096.0f * 2.8284271247461903f);
        float g0 = Gs[w * 64 + l], g1 = Gs[w * 64 + l + 32];
        float m1i = m1s[i0 + w], m1l = m1s[l], m1l2 = m1s[l + 32];
        float acc0 = 0.f, acc1 = 0.f;
        #pragma unroll
        for (int h = 0; h < 4; ++h) {
            float al = sal[h] * scale, be = sbe[h] * scale;
            float ga = sga[h] * scale, de = sde[h] * scale * 4096.f;
            float whh = swh[h];
            float base = be * m1i + de;
            float s0 = al * g0 + ga * m1l  + base;
            float s1 = al * g1 + ga * m1l2 + base;
            float mx = fmaxf(s0, s1);
            #pragma unroll
            for (int off = 16; off > 0; off >>= 1)
                mx = fmaxf(mx, __shfl_xor_sync(0xffffffffu, mx, off));
            float e0 = __expf(s0 - mx), e1 = __expf(s1 - mx);
            float sm = e0 + e1;
            #pragma unroll
            for (int off = 16; off > 0; off >>= 1)
                sm += __shfl_xor_sync(0xffffffffu, sm, off);
            float f = whh / sm;
            acc0 += e0 * f; acc1 += e1 * f;
        }
        // transposed + duplicated store: g_Mdup[b][j][2i] = {M[i][j], M[i][j]}
        int i = i0 + w;
        float* mo = &g_Mdup[b * 8192];
        *(float2*)(mo + l * 128 + 2 * i)        = make_float2(acc0, acc0);
        *(float2*)(mo + (l + 32) * 128 + 2 * i) = make_float2(acc1, acc1);
    }
}

// ---------------- K3: out = M @ X + const ----------------
// grid 512 (b*64+y), 128 threads. Md[j][2s] pre-duplicated (broadcast LDS.128,
// zero movs); V[j][x] natural layout (conflict-free fill and reads).
__global__ __launch_bounds__(128) void out_kernel(const float* __restrict__ x,
                                                  float* __restrict__ out) {
    int b = blockIdx.x >> 6, y = blockIdx.x & 63;
    __shared__ __align__(16) float Md[64 * 128];
    __shared__ __align__(16) float V[64 * 64];
    int tid = threadIdx.x;

    const float4* mg = (const float4*)&g_Mdup[b * 8192];
    #pragma unroll
    for (int t = 0; t < 16; ++t)
        ((float4*)Md)[tid + 128 * t] = mg[tid + 128 * t];

    const float* xb = x + b * 262144 + y * 512;
    #pragma unroll
    for (int t = 0; t < 8; ++t) {
        int i4 = tid + 128 * t;
        int j = i4 >> 4, c = i4 & 15;
        ((float4*)V)[i4] = *(const float4*)(xb + (j >> 3) * 32768 + (j & 7) * 64 + 4 * c);
    }
    __syncthreads();

    int ti = tid >> 4, tj = tid & 15;
    ull acc[8][2];
    #pragma unroll
    for (int u = 0; u < 8; ++u) { acc[u][0] = 0ull; acc[u][1] = 0ull; }

    #pragma unroll 4
    for (int j = 0; j < 64; ++j) {
        ulonglong2 bv = *(const ulonglong2*)&V[j * 64 + 4 * tj];     // x-pairs
        const ull* md = (const ull*)&Md[j * 128 + 16 * ti];          // 8 dup rows
        ulonglong2 m0 = *(const ulonglong2*)(md);
        ulonglong2 m1 = *(const ulonglong2*)(md + 2);
        ulonglong2 m2 = *(const ulonglong2*)(md + 4);
        ulonglong2 m3 = *(const ulonglong2*)(md + 6);
        ffma2(acc[0][0], m0.x, bv.x); ffma2(acc[0][1], m0.x, bv.y);
        ffma2(acc[1][0], m0.y, bv.x); ffma2(acc[1][1], m0.y, bv.y);
        ffma2(acc[2][0], m1.x, bv.x); ffma2(acc[2][1], m1.x, bv.y);
        ffma2(acc[3][0], m1.y, bv.x); ffma2(acc[3][1], m1.y, bv.y);
        ffma2(acc[4][0], m2.x, bv.x); ffma2(acc[4][1], m2.x, bv.y);
        ffma2(acc[5][0], m2.y, bv.x); ffma2(acc[5][1], m2.y, bv.y);
        ffma2(acc[6][0], m3.x, bv.x); ffma2(acc[6][1], m3.x, bv.y);
        ffma2(acc[7][0], m3.y, bv.x); ffma2(acc[7][1], m3.y, bv.y);
    }

    float cst = g_cst[0];
    ull c2 = pack2(cst, cst);
    float* ob = out + b * 262144 + y * 512;
    #pragma unroll
    for (int u = 0; u < 8; ++u) {
        int s = 8 * ti + u;
        float* dst = ob + (s >> 3) * 32768 + (s & 7) * 64 + 4 * tj;
        *(ulonglong2*)dst = make_ulonglong2(add2(acc[u][0], c2), add2(acc[u][1], c2));
    }
}

extern "C" void kernel_launch(void* const* d_in, const int* in_sizes, int n_in,
                              void* d_out, int out_size) {
    const float* x     = (const float*)d_in[0];
    const float* w1    = (const float*)d_in[3];
    const float* b1    = (const float*)d_in[4];
    const float* wqkv  = (const float*)d_in[5];
    const float* wproj = (const float*)d_in[6];
    const float* bproj = (const float*)d_in[7];
    const float* w2    = (const float*)d_in[8];
    const float* b2    = (const float*)d_in[9];
    float* out = (float*)d_out;

    gram_kernel<<<512, 128>>>(x);
    attn_kernel<<<dim3(8, 16), 256>>>(w1, b1, wqkv, wproj, bproj, w2, b2);
    out_kernel<<<512, 128>>>(x, out);
}

// round 9
// speedup vs baseline: 1.2994x; 1.2994x over previous
#include <cuda_runtime.h>
#include <cuda_bf16.h>
#include <cstdint>

typedef unsigned long long ull;

// ---------------- scratch ----------------
__device__ float g_Gpart[8 * 32 * 64 * 64];        // split-K gram partials (4 MB)
__device__ float g_m1part[8 * 32 * 64];            // token-sum partials
__device__ __nv_bfloat16 g_Mbf[8 * 64 * 128];      // mixing matrix split [b][s][Mh(64)|Ml(64)]
__device__ float g_cst[1];

__device__ __forceinline__ uint32_t smem_u32(const void* p) {
    uint32_t a;
    asm("{ .reg .u64 t; cvta.to.shared.u64 t, %1; cvt.u32.u64 %0, t; }" : "=r"(a) : "l"(p));
    return a;
}
__device__ __forceinline__ void ldsm4(uint32_t& r0, uint32_t& r1, uint32_t& r2, uint32_t& r3,
                                      uint32_t addr) {
    asm volatile("ldmatrix.sync.aligned.m8n8.x4.shared.b16 {%0,%1,%2,%3}, [%4];"
                 : "=r"(r0), "=r"(r1), "=r"(r2), "=r"(r3) : "r"(addr));
}
__device__ __forceinline__ void mma_bf16(float c[4], uint32_t a0, uint32_t a1, uint32_t a2,
                                         uint32_t a3, uint32_t b0, uint32_t b1) {
    asm volatile(
        "mma.sync.aligned.m16n8k16.row.col.f32.bf16.bf16.f32 "
        "{%0,%1,%2,%3}, {%4,%5,%6,%7}, {%8,%9}, {%0,%1,%2,%3};"
        : "+f"(c[0]), "+f"(c[1]), "+f"(c[2]), "+f"(c[3])
        : "r"(a0), "r"(a1), "r"(a2), "r"(a3), "r"(b0), "r"(b1));
}

// padded bf16 tile row stride: 136 halves (272 B) -> conflict-free ldmatrix
#define TSTRIDE 136

// ---------------- K1: Gram via HMMA ----------------
// grid 256 (b*32 + chunk of 2 image rows = 128 k), 256 threads (8 warps).
// Hi/Lo[token 64][k 128] bf16. Warps 0-3: C1 = Hi*Hi^T strips; 4-7: C2 = Hi*Lo^T.
// G = C1 + C2 + C2^T   (drops Lo*Lo^T ~ 2^-18).
__global__ __launch_bounds__(256) void gram_kernel(const float* __restrict__ x) {
    __shared__ __align__(16) unsigned char pool[2 * 64 * TSTRIDE * 2]; // Hi|Lo, later Gs|Cs
    __shared__ float m1w[8][64];

    int b = blockIdx.x >> 5, chunk = blockIdx.x & 31;
    int tid = threadIdx.x, w = tid >> 5, l = tid & 31;
    __nv_bfloat16* Hi = (__nv_bfloat16*)pool;
    __nv_bfloat16* Lo = Hi + 64 * TSTRIDE;
    uint32_t hi_b = smem_u32(pool);
    uint32_t lo_b = hi_b + 64 * TSTRIDE * 2;

    m1w[w][l] = 0.f; m1w[w][l + 32] = 0.f;

    const float* xb = x + b * 262144;
    #pragma unroll
    for (int it = 0; it < 8; ++it) {
        int f4 = it * 256 + tid;
        int row = f4 >> 7, x4 = f4 & 127;          // row: 8 token-rows x 2 ysl
        int i = row >> 1, ysl = row & 1;
        int h = i * 64 + chunk * 2 + ysl;
        float4 v = *(const float4*)(xb + h * 512 + x4 * 4);
        int j = i * 8 + (x4 >> 4);
        int k = ysl * 64 + (x4 & 15) * 4;
        __nv_bfloat162 h01 = __float22bfloat162_rn(make_float2(v.x, v.y));
        __nv_bfloat162 h23 = __float22bfloat162_rn(make_float2(v.z, v.w));
        float2 f01 = __bfloat1622float2(h01);
        float2 f23 = __bfloat1622float2(h23);
        __nv_bfloat162 l01 = __float22bfloat162_rn(make_float2(v.x - f01.x, v.y - f01.y));
        __nv_bfloat162 l23 = __float22bfloat162_rn(make_float2(v.z - f23.x, v.w - f23.y));
        *(uint2*)&Hi[j * TSTRIDE + k] = make_uint2(*(uint32_t*)&h01, *(uint32_t*)&h23);
        *(uint2*)&Lo[j * TSTRIDE + k] = make_uint2(*(uint32_t*)&l01, *(uint32_t*)&l23);
        float s4 = (v.x + v.y) + (v.z + v.w);
        s4 += __shfl_xor_sync(0xffffffffu, s4, 1);
        s4 += __shfl_xor_sync(0xffffffffu, s4, 2);
        s4 += __shfl_xor_sync(0xffffffffu, s4, 4);
        s4 += __shfl_xor_sync(0xffffffffu, s4, 8);
        if ((l & 15) == 0) m1w[w][j] += s4;
    }
    __syncthreads();

    if (tid < 64) {
        float s = 0.f;
        #pragma unroll
        for (int ww = 0; ww < 8; ++ww) s += m1w[ww][tid];
        g_m1part[(b * 32 + chunk) * 64 + tid] = s;
    }

    uint32_t sB = (w < 4) ? hi_b : lo_b;
    int r0 = 16 * (w & 3);
    float c[8][4];
    #pragma unroll
    for (int t = 0; t < 8; ++t)
        #pragma unroll
        for (int q = 0; q < 4; ++q) c[t][q] = 0.f;

    int arow = r0 + (l & 15), ak = (l >> 4) << 3;
    int brow = ((l >> 4) << 3) + (l & 7), bk = ((l >> 3) & 1) << 3;

    #pragma unroll
    for (int kk = 0; kk < 128; kk += 16) {
        uint32_t a0, a1, a2, a3;
        ldsm4(a0, a1, a2, a3, hi_b + (arow * TSTRIDE + kk + ak) * 2);
        #pragma unroll
        for (int t = 0; t < 4; ++t) {
            uint32_t b0, b1, b2, b3;
            ldsm4(b0, b1, b2, b3, sB + ((16 * t + brow) * TSTRIDE + kk + bk) * 2);
            mma_bf16(c[2 * t],     a0, a1, a2, a3, b0, b1);
            mma_bf16(c[2 * t + 1], a0, a1, a2, a3, b2, b3);
        }
    }
    __syncthreads();   // all ldmatrix done -> safe to alias pool as float Gs/Cs

    float* Gs = (float*)pool;                 // C1 [64][68]
    float* Cs = Gs + 64 * 68;                 // C2 [64][68]
    float* Cw = (w < 4) ? Gs : Cs;
    int er = r0 + (l >> 2), ec = 2 * (l & 3);
    #pragma unroll
    for (int t = 0; t < 8; ++t) {
        Cw[er * 68 + 8 * t + ec]           = c[t][0];
        Cw[er * 68 + 8 * t + ec + 1]       = c[t][1];
        Cw[(er + 8) * 68 + 8 * t + ec]     = c[t][2];
        Cw[(er + 8) * 68 + 8 * t + ec + 1] = c[t][3];
    }
    __syncthreads();

    float* gp = &g_Gpart[(b * 32 + chunk) * 4096];
    #pragma unroll
    for (int it = 0; it < 16; ++it) {
        int idx = it * 256 + tid;
        int i = idx >> 6, j = idx & 63;
        gp[idx] = Gs[i * 68 + j] + Cs[i * 68 + j] + Cs[j * 68 + i];
    }
}

// ---------------- K2: consts + reduce + softmax + split-bf16 M ----------------
// grid (8, 16 groups of 4 rows), 256 threads.
__global__ __launch_bounds__(256) void attn_kernel(
        const float* __restrict__ w1, const float* __restrict__ b1,
        const float* __restrict__ wqkv, const float* __restrict__ wproj,
        const float* __restrict__ bproj, const float* __restrict__ w2,
        const float* __restrict__ b2) {
    int b = blockIdx.x, i0 = blockIdx.y * 4, tid = threadIdx.x;
    __shared__ float A[96], B0[96], tC[32];
    __shared__ float sal[4], sbe[4], sga[4], sde[4], swh[4];
    __shared__ float Gs[256], m1s[64];

    if (tid < 96) {
        float a = 0.f, bb = 0.f;
        #pragma unroll
        for (int c = 0; c < 32; ++c) {
            float wv = wqkv[tid * 32 + c];
            a += wv * w1[c];
            bb += wv * b1[c];
        }
        A[tid] = a; B0[tid] = bb;
    }
    if (tid >= 128 && tid < 160) {
        int c = tid - 128;
        float s = 0.f;
        #pragma unroll
        for (int o = 0; o < 32; ++o) s += w2[o] * wproj[o * 32 + c];
        tC[c] = s;
    }
    __syncthreads();
    if (tid < 4) {
        float al = 0.f, be = 0.f, ga = 0.f, de = 0.f, wh = 0.f;
        #pragma unroll
        for (int dd = 0; dd < 8; ++dd) {
            int c = tid * 8 + dd;
            float aq = A[c], ak = A[32 + c], bq = B0[c], bk = B0[32 + c];
            al += aq * ak; be += aq * bk; ga += bq * ak; de += bq * bk;
            wh += tC[c] * A[64 + c];
        }
        sal[tid] = al; sbe[tid] = be; sga[tid] = ga; sde[tid] = de; swh[tid] = wh;
    }
    if (tid == 4) {
        float c = b2[0];
        #pragma unroll
        for (int o = 0; o < 32; ++o) c += w2[o] * bproj[o];
        #pragma unroll
        for (int cc = 0; cc < 32; ++cc) c += tC[cc] * B0[64 + cc];
        g_cst[0] = c;
    }

    {
        const float* gp = &g_Gpart[b * 32 * 4096 + i0 * 64];
        float s = 0.f;
        #pragma unroll 8
        for (int c = 0; c < 32; ++c) s += gp[c * 4096 + tid];
        Gs[tid] = s;
    }
    if (tid < 64) {
        const float* mp = &g_m1part[b * 32 * 64];
        float s = 0.f;
        #pragma unroll 8
        for (int c = 0; c < 32; ++c) s += mp[c * 64 + tid];
        m1s[tid] = s;
    }
    __syncthreads();

    int w = tid >> 5, l = tid & 31;
    if (w < 4) {
        const float scale = 1.0f / (4096.0f * 2.8284271247461903f);
        float g0 = Gs[w * 64 + l], g1 = Gs[w * 64 + l + 32];
        float m1i = m1s[i0 + w], m1l = m1s[l], m1l2 = m1s[l + 32];
        float acc0 = 0.f, acc1 = 0.f;
        #pragma unroll
        for (int h = 0; h < 4; ++h) {
            float al = sal[h] * scale, be = sbe[h] * scale;
            float ga = sga[h] * scale, de = sde[h] * scale * 4096.f;
            float whh = swh[h];
            float base = be * m1i + de;
            float s0 = al * g0 + ga * m1l  + base;
            float s1 = al * g1 + ga * m1l2 + base;
            float mx = fmaxf(s0, s1);
            #pragma unroll
            for (int off = 16; off > 0; off >>= 1)
                mx = fmaxf(mx, __shfl_xor_sync(0xffffffffu, mx, off));
            float e0 = __expf(s0 - mx), e1 = __expf(s1 - mx);
            float sm = e0 + e1;
            #pragma unroll
            for (int off = 16; off > 0; off >>= 1)
                sm += __shfl_xor_sync(0xffffffffu, sm, off);
            float f = whh / sm;
            acc0 += e0 * f; acc1 += e1 * f;
        }
        // split-bf16 store: [b][i][ Mh(64) | Ml(64) ]
        int i = i0 + w;
        __nv_bfloat16* mo = &g_Mbf[b * 8192 + i * 128];
        __nv_bfloat16 h0 = __float2bfloat16(acc0);
        __nv_bfloat16 h1 = __float2bfloat16(acc1);
        mo[l]           = h0;
        mo[64 + l]      = __float2bfloat16(acc0 - __bfloat162float(h0));
        mo[l + 32]      = h1;
        mo[64 + l + 32] = __float2bfloat16(acc1 - __bfloat162float(h1));
    }
}

// ---------------- K3: out = M @ X + const via HMMA ----------------
// grid 512 (b*64+y), 256 threads. Asm=[Mh|Ml] 64x128, Bsm=[Xh|Xl] per-x rows.
// 12 k16 iterations: Mh*Xh (0-3), Ml*Xh (4-7), Mh*Xl (8-11); drops Ml*Xl ~2^-18.
__global__ __launch_bounds__(256) void out_kernel(const float* __restrict__ x,
                                                  float* __restrict__ out) {
    __shared__ __align__(16) __nv_bfloat16 Asm[64 * TSTRIDE];
    __shared__ __align__(16) __nv_bfloat16 Bsm[64 * TSTRIDE];

    int b = blockIdx.x >> 6, y = blockIdx.x & 63;
    int tid = threadIdx.x, w = tid >> 5, l = tid & 31;
    uint32_t a_b = smem_u32(Asm), b_b = smem_u32(Bsm);

    // load A (64 x [Mh|Ml]) with padded stride
    const uint4* mg = (const uint4*)&g_Mbf[b * 8192];
    #pragma unroll
    for (int it = 0; it < 4; ++it) {
        int u = it * 256 + tid;
        int row = u >> 4, c8 = (u & 15) * 8;
        *(uint4*)&Asm[row * TSTRIDE + c8] = mg[u];
    }

    // convert X row y -> Bsm[x][ j (hi) | 64+j (lo) ]
    const float* xb = x + b * 262144;
    #pragma unroll
    for (int it = 0; it < 4; ++it) {
        int f4 = it * 256 + tid;
        int j = f4 >> 4, x4 = f4 & 15;
        float4 v = *(const float4*)(xb + ((j >> 3) * 64 + y) * 512 + (j & 7) * 64 + x4 * 4);
        float vv[4] = {v.x, v.y, v.z, v.w};
        #pragma unroll
        for (int d = 0; d < 4; ++d) {
            __nv_bfloat16 h = __float2bfloat16(vv[d]);
            Bsm[(x4 * 4 + d) * TSTRIDE + j]      = h;
            Bsm[(x4 * 4 + d) * TSTRIDE + 64 + j] = __float2bfloat16(vv[d] - __bfloat162float(h));
        }
    }
    __syncthreads();

    // warp (rw, nh): rows 16*rw, cols nh*32..+31
    int rw = w & 3, nh = w >> 2;
    int r0 = 16 * rw;
    float c[4][4];
    #pragma unroll
    for (int t = 0; t < 4; ++t)
        #pragma unroll
        for (int q = 0; q < 4; ++q) c[t][q] = 0.f;

    int arow = r0 + (l & 15), ak = (l >> 4) << 3;
    int brow = ((l >> 4) << 3) + (l & 7), bk = ((l >> 3) & 1) << 3;

    #pragma unroll
    for (int it = 0; it < 12; ++it) {
        // term mapping: 0-3 Mh*Xh, 4-7 Ml*Xh, 8-11 Mh*Xl
        int ka = (it < 4) ? it * 16 : (it < 8 ? 64 + (it - 4) * 16 : (it - 8) * 16);
        int kb = (it < 8) ? (it & 3) * 16 : 64 + (it - 8) * 16;
        uint32_t a0, a1, a2, a3;
        ldsm4(a0, a1, a2, a3, a_b + (arow * TSTRIDE + ka + ak) * 2);
        #pragma unroll
        for (int t = 0; t < 2; ++t) {
            int n0 = nh * 32 + 16 * t;
            uint32_t b0, b1, b2, b3;
            ldsm4(b0, b1, b2, b3, b_b + ((n0 + brow) * TSTRIDE + kb + bk) * 2);
            mma_bf16(c[2 * t],     a0, a1, a2, a3, b0, b1);
            mma_bf16(c[2 * t + 1], a0, a1, a2, a3, b2, b3);
        }
    }

    float cst = g_cst[0];
    float* ob = out + b * 262144;
    int er = r0 + (l >> 2), ec = 2 * (l & 3);
    #pragma unroll
    for (int t = 0; t < 4; ++t) {
        int col = nh * 32 + 8 * t + ec;
        int s0 = er, s1 = er + 8;
        *(float2*)&ob[((s0 >> 3) * 64 + y) * 512 + (s0 & 7) * 64 + col] =
            make_float2(c[t][0] + cst, c[t][1] + cst);
        *(float2*)&ob[((s1 >> 3) * 64 + y) * 512 + (s1 & 7) * 64 + col] =
            make_float2(c[t][2] + cst, c[t][3] + cst);
    }
}

extern "C" void kernel_launch(void* const* d_in, const int* in_sizes, int n_in,
                              void* d_out, int out_size) {
    const float* x     = (const float*)d_in[0];
    const float* w1    = (const float*)d_in[3];
    const float* b1    = (const float*)d_in[4];
    const float* wqkv  = (const float*)d_in[5];
    const float* wproj = (const float*)d_in[6];
    const float* bproj = (const float*)d_in[7];
    const float* w2    = (const float*)d_in[8];
    const float* b2    = (const float*)d_in[9];
    float* out = (float*)d_out;

    gram_kernel<<<256, 256>>>(x);
    attn_kernel<<<dim3(8, 16), 256>>>(w1, b1, wqkv, wproj, bproj, w2, b2);
    out_kernel<<<512, 256>>>(x, out);
}